// round 14
// baseline (speedup 1.0000x reference)
#include <cuda_runtime.h>
#include <cuda_bf16.h>

// Problem constants: P=Q=3, M=N=127, DIM=3, SU=SV=256, B=16
#define PB    16
#define PDEG  3
#define PM    127
#define PL    132
#define PS    256
#define PNC   128
#define PDIM  3
#define PEPS  1e-8f
#define TUC   4            // u's per block
#define SROWS 8            // staged ctrl rows
#define ROWF  (PNC * PDIM) // 384 floats per raw ctrl row
#define ROWV4 (ROWF / 4)   // 96
#define NRAW  (SROWS * ROWV4)  // 768 float4 raw window

typedef unsigned long long ull;

__device__ __forceinline__ ull pack2(float lo, float hi) {
    ull r; asm("mov.b64 %0, {%1, %2};" : "=l"(r) : "f"(lo), "f"(hi)); return r;
}
__device__ __forceinline__ void unpack2(ull p, float& lo, float& hi) {
    asm("mov.b64 {%0, %1}, %2;" : "=f"(lo), "=f"(hi) : "l"(p));
}
__device__ __forceinline__ ull fma2(ull a, ull b, ull c) {
    ull d; asm("fma.rn.f32x2 %0, %1, %2, %3;" : "=l"(d) : "l"(a), "l"(b), "l"(c)); return d;
}
__device__ __forceinline__ ull mul2(ull a, ull b) {
    ull d; asm("mul.rn.f32x2 %0, %1, %2;" : "=l"(d) : "l"(a), "l"(b)); return d;
}

// ---------------------------------------------------------------------------
// One warp normalizes one knot vector (register scan), writes sK.
// ---------------------------------------------------------------------------
__device__ __forceinline__ void warp_scan_knots(const float* __restrict__ knots,
                                                float* __restrict__ sK)
{
    const int lane = threadIdx.x & 31;
    const int CH = 5;
    const int base = lane * CH;
    float vch[CH];
    float run = 0.0f;
    #pragma unroll
    for (int k = 0; k < CH; k++) {
        int i = base + k;
        float x = 0.0f;
        if (i < PL) {
            x = knots[i];
            if (x < 0.0f) x = 0.0001f;
        }
        run += x;
        vch[k] = run;
    }
    float incl = run;
    #pragma unroll
    for (int off = 1; off < 32; off <<= 1) {
        float nb = __shfl_up_sync(0xffffffffu, incl, off);
        if (lane >= off) incl += nb;
    }
    const float excl = incl - run;
    const float sc0  = excl + vch[0];
    const float k0   = __shfl_sync(0xffffffffu, sc0, 0);
    const float last = __shfl_sync(0xffffffffu, incl, 31);
    const float inv  = 1.0f / (last - k0);
    #pragma unroll
    for (int k = 0; k < CH; k++) {
        int i = base + k;
        if (i < PL) sK[i] = ((excl + vch[k]) - k0) * inv;
    }
}

// span find (binary search + tie-walk, argmin semantics) + Cox-de Boor deg 3
__device__ __forceinline__ int basis_at(const float* sK, float t, float* Ni)
{
    int j;
    {
        const int cnt = PL - 2 * PDEG;
        int lo = 0, hi = cnt;
        while (lo < hi) {
            int mid = (lo + hi) >> 1;
            if (t - sK[PDEG + mid] > PEPS) lo = mid + 1;
            else hi = mid;
        }
        j = lo - 1;
        if (j < 0) j = 0;
        else {
            while (j > 0 && sK[PDEG + j - 1] == sK[PDEG + j]) j--;
        }
    }
    int span = j + PDEG;
    if (span < PDEG) span = PDEG;
    if (span > PM)   span = PM;

    Ni[0] = 1.0f; Ni[1] = 0.0f; Ni[2] = 0.0f; Ni[3] = 0.0f;
    #pragma unroll
    for (int k = 1; k <= PDEG; k++) {
        float saved = 0.0f;
        #pragma unroll
        for (int r = 0; r < PDEG; r++) {
            if (r >= k) break;
            float K1 = sK[span + r + 1];
            float K2 = sK[span + 1 - k + r];
            float denom = (K1 - t) + (t - K2);
            float temp = (denom == 0.0f) ? 0.0001f : __fdividef(Ni[r], denom);
            Ni[r] = saved + (K1 - t) * temp;
            saved = (t - K2) * temp;
        }
        Ni[k] = saved;
    }
    return span;
}

// ---------------------------------------------------------------------------
// Fused kernel. grid = B*(PS/TUC) = 1024 blocks, blockDim = 256 (thread=vv).
// ---------------------------------------------------------------------------
__global__ void __launch_bounds__(PS, 5)
surf_fused_kernel(const float* __restrict__ ctrl,
                  const float* __restrict__ knot_u,
                  const float* __restrict__ knot_v,
                  const float* __restrict__ u,
                  const float* __restrict__ v,
                  float* __restrict__ out)
{
    const int b   = blockIdx.x / (PS / TUC);
    const int u0  = (blockIdx.x % (PS / TUC)) * TUC;
    const int vv  = threadIdx.x;
    const int tid = threadIdx.x;
    const int wid = tid >> 5;

    __shared__ float  sKv[PL];
    __shared__ float  sKu[PL];
    __shared__ int    s_iu[TUC];
    __shared__ float  s_nu[TUC][PDEG + 1];
    __shared__ ull    s_w2[SROWS][TUC];          // packed {w,w}
    __shared__ float  s_w1[SROWS][TUC];          // scalar w (z channel)
    __shared__ float4 sCp[SROWS * PNC];          // 16 KB padded points
    __shared__ float  sScr[SROWS * ROWF];        // 12 KB raw stage / out stage

    // warp 0 scans v-knots; warp 1 scans u-knots then u-basis (4 lanes)
    if (wid == 0) {
        warp_scan_knots(knot_v + b * PL, sKv);
    } else if (wid == 1) {
        warp_scan_knots(knot_u + b * PL, sKu);
        __syncwarp();
        const int li = tid & 31;
        if (li < TUC) {
            float nu[PDEG + 1];
            const int us = basis_at(sKu, u[u0 + li], nu);
            s_iu[li] = us - PDEG;
            #pragma unroll
            for (int p = 0; p <= PDEG; p++) s_nu[li][p] = nu[p];
        }
    }
    __syncthreads();

    const float4* cb4 = (const float4*)(ctrl + (long)b * PNC * ROWF);

    // prefetch first window raw (coalesced), overlapping the v-basis chain
    const int rlo0 = s_iu[0];
    float4 pf[3];
    #pragma unroll
    for (int k = 0; k < 3; k++) {
        const int idx = tid + k * PS;
        const int j = idx / ROWV4, t4 = idx % ROWV4;
        const int row = min(rlo0 + j, PNC - 1);
        pf[k] = __ldg(&cb4[(long)row * ROWV4 + t4]);
    }

    // v-basis (per thread, parallel; overlaps LDGs above)
    int iv;
    ull nv2[PDEG + 1];
    float nvz[PDEG + 1];
    {
        float nv[PDEG + 1];
        iv = basis_at(sKv, v[vv], nv) - PDEG;
        #pragma unroll
        for (int q = 0; q <= PDEG; q++) { nv2[q] = pack2(nv[q], nv[q]); nvz[q] = nv[q]; }
    }

    ull   accXY[TUC];
    float accZ[TUC];
    #pragma unroll
    for (int i = 0; i < TUC; i++) { accXY[i] = pack2(0.0f, 0.0f); accZ[i] = 0.0f; }

    int done = 0;
    bool first = true;
    while (done < TUC) {
        const int rlo = s_iu[done];
        int gend = done;
        while (gend + 1 < TUC && s_iu[gend + 1] + PDEG - rlo < SROWS) gend++;

        if (!first) __syncthreads();            // prior reads of sCp/s_w done

        // weight tables (zero-padded)
        if (tid < SROWS * TUC) {
            const int j = tid / TUC, i = tid % TUC;
            float w = 0.0f;
            if (i >= done && i <= gend) {
                const int p = (rlo + j) - s_iu[i];
                if (p >= 0 && p <= PDEG) w = s_nu[i][p];
            }
            s_w1[j][i] = w;
            s_w2[j][i] = pack2(w, w);
        }

        // raw stage into sScr
        if (first) {
            #pragma unroll
            for (int k = 0; k < 3; k++)
                ((float4*)sScr)[tid + k * PS] = pf[k];
        } else {
            #pragma unroll
            for (int k = 0; k < 3; k++) {
                const int idx = tid + k * PS;
                const int j = idx / ROWV4, t4 = idx % ROWV4;
                const int row = min(rlo + j, PNC - 1);
                ((float4*)sScr)[idx] = cb4[(long)row * ROWV4 + t4];
            }
        }
        __syncthreads();

        // repack raw (12B points) -> padded float4 points in sCp
        // thread handles global points [4*tid .. 4*tid+3]; raw floats 12t..12t+11
        {
            const float4 ra = ((const float4*)sScr)[3 * tid + 0];
            const float4 rb = ((const float4*)sScr)[3 * tid + 1];
            const float4 rc = ((const float4*)sScr)[3 * tid + 2];
            sCp[4 * tid + 0] = make_float4(ra.x, ra.y, ra.z, 0.0f);
            sCp[4 * tid + 1] = make_float4(ra.w, rb.x, rb.y, 0.0f);
            sCp[4 * tid + 2] = make_float4(rb.z, rb.w, rc.x, 0.0f);
            sCp[4 * tid + 3] = make_float4(rc.y, rc.z, rc.w, 0.0f);
        }
        __syncthreads();

        // main loop: 8 rows, f32x2 v-contract + f32x2 fanout
        #pragma unroll
        for (int j = 0; j < SROWS; j++) {
            const float4* pw = &sCp[j * PNC + iv];
            const float4 q0 = pw[0];
            const float4 q1 = pw[1];
            const float4 q2 = pw[2];
            const float4 q3 = pw[3];
            ull rxy = mul2(nv2[0], pack2(q0.x, q0.y));
            rxy = fma2(nv2[1], pack2(q1.x, q1.y), rxy);
            rxy = fma2(nv2[2], pack2(q2.x, q2.y), rxy);
            rxy = fma2(nv2[3], pack2(q3.x, q3.y), rxy);
            float rz = nvz[0] * q0.z;
            rz = fmaf(nvz[1], q1.z, rz);
            rz = fmaf(nvz[2], q2.z, rz);
            rz = fmaf(nvz[3], q3.z, rz);
            #pragma unroll
            for (int i = 0; i < TUC; i++) {
                accXY[i] = fma2(s_w2[j][i], rxy, accXY[i]);   // LDS.64 broadcast
                accZ[i]  = fmaf(s_w1[j][i], rz, accZ[i]);
            }
        }

        first = false;
        done = gend + 1;
    }

    // stage outputs in sScr (3072 floats = 4 u-rows x 256 vv x 3), then
    // fully coalesced float4 stores.
    __syncthreads();
    #pragma unroll
    for (int i = 0; i < TUC; i++) {
        float x, y; unpack2(accXY[i], x, y);
        float* so = sScr + (i * PS + vv) * PDIM;
        so[0] = x; so[1] = y; so[2] = accZ[i];
    }
    __syncthreads();

    float4* og = (float4*)(out + ((long)b * PS + u0) * PS * PDIM);
    #pragma unroll
    for (int k = 0; k < 3; k++)
        og[tid + k * PS] = ((const float4*)sScr)[tid + k * PS];
}

// ---------------------------------------------------------------------------
extern "C" void kernel_launch(void* const* d_in, const int* in_sizes, int n_in,
                              void* d_out, int out_size)
{
    const float* ctrl   = (const float*)d_in[0];  // (B, 128, 128, 3)
    const float* knot_u = (const float*)d_in[1];  // (B, 132)
    const float* knot_v = (const float*)d_in[2];  // (B, 132)
    const float* u      = (const float*)d_in[3];  // (256,)
    const float* v      = (const float*)d_in[4];  // (256,)
    float* out = (float*)d_out;                   // (B, 256, 256, 3)

    surf_fused_kernel<<<PB * (PS / TUC), PS>>>(ctrl, knot_u, knot_v, u, v, out);
}

// round 15
// speedup vs baseline: 1.3907x; 1.3907x over previous
#include <cuda_runtime.h>
#include <cuda_bf16.h>

// Problem constants: P=Q=3, M=N=127, DIM=3, SU=SV=256, B=16
#define PB    16
#define PDEG  3
#define PM    127
#define PL    132          // knot vector length
#define PS    256          // samples per direction
#define PNC   128          // control points per direction
#define PDIM  3
#define PEPS  1e-8f
#define TUC   8            // u's per block
#define SROWS 12           // staged ctrl rows in shared
#define ROWF  (PNC * PDIM) // floats per ctrl row (384)
#define ROWV4 (ROWF / 4)   // float4 per ctrl row (96)

// ---------------------------------------------------------------------------
// One warp normalizes one knot vector entirely in registers, writes sK.
// cumsum order matches jnp.cumsum (sequential within chunk, chunks in order).
// ---------------------------------------------------------------------------
__device__ __forceinline__ void warp_scan_knots(const float* __restrict__ knots,
                                                float* __restrict__ sK)
{
    const int lane = threadIdx.x & 31;
    const int CH = 5;                           // 32*5 >= 132
    const int base = lane * CH;
    float vch[CH];
    float run = 0.0f;
    #pragma unroll
    for (int k = 0; k < CH; k++) {
        int i = base + k;
        float x = 0.0f;
        if (i < PL) {
            x = knots[i];
            if (x < 0.0f) x = 0.0001f;
        }
        run += x;
        vch[k] = run;
    }
    float incl = run;
    #pragma unroll
    for (int off = 1; off < 32; off <<= 1) {
        float nb = __shfl_up_sync(0xffffffffu, incl, off);
        if (lane >= off) incl += nb;
    }
    const float excl = incl - run;
    const float sc0  = excl + vch[0];
    const float k0   = __shfl_sync(0xffffffffu, sc0, 0);
    const float last = __shfl_sync(0xffffffffu, incl, 31);   // cumsum[131]
    const float inv  = 1.0f / (last - k0);
    #pragma unroll
    for (int k = 0; k < CH; k++) {
        int i = base + k;
        if (i < PL) sK[i] = ((excl + vch[k]) - k0) * inv;
    }
}

// span find (binary search + tie-walk, argmin semantics) + Cox-de Boor deg 3
__device__ __forceinline__ int basis_at(const float* sK, float t, float* Ni)
{
    int j;
    {
        const int cnt = PL - 2 * PDEG;          // 126
        int lo = 0, hi = cnt;
        while (lo < hi) {
            int mid = (lo + hi) >> 1;
            if (t - sK[PDEG + mid] > PEPS) lo = mid + 1;
            else hi = mid;
        }
        j = lo - 1;
        if (j < 0) j = 0;
        else {
            while (j > 0 && sK[PDEG + j - 1] == sK[PDEG + j]) j--;
        }
    }
    int span = j + PDEG;
    if (span < PDEG) span = PDEG;
    if (span > PM)   span = PM;

    Ni[0] = 1.0f; Ni[1] = 0.0f; Ni[2] = 0.0f; Ni[3] = 0.0f;
    #pragma unroll
    for (int k = 1; k <= PDEG; k++) {
        float saved = 0.0f;
        #pragma unroll
        for (int r = 0; r < PDEG; r++) {
            if (r >= k) break;
            float K1 = sK[span + r + 1];
            float K2 = sK[span + 1 - k + r];
            float denom = (K1 - t) + (t - K2);
            float temp = (denom == 0.0f) ? 0.0001f : __fdividef(Ni[r], denom);
            Ni[r] = saved + (K1 - t) * temp;
            saved = (t - K2) * temp;
        }
        Ni[k] = saved;
    }
    return span;
}

// ---------------------------------------------------------------------------
// Fused kernel: basis + coalesced ctrl staging + v-contract + u-fanout.
// grid = B * (PS/TUC) = 512 blocks, blockDim = 256 (thread = vv).
// ---------------------------------------------------------------------------
__global__ void __launch_bounds__(PS)
surf_fused_kernel(const float* __restrict__ ctrl,
                  const float* __restrict__ knot_u,
                  const float* __restrict__ knot_v,
                  const float* __restrict__ u,
                  const float* __restrict__ v,
                  float* __restrict__ out)
{
    const int b   = blockIdx.x / (PS / TUC);
    const int u0  = (blockIdx.x % (PS / TUC)) * TUC;
    const int vv  = threadIdx.x;
    const int tid = threadIdx.x;
    const int wid = tid >> 5;

    __shared__ float sKv[PL];
    __shared__ float sKu[PL];
    __shared__ int   s_iu[TUC];
    __shared__ float s_nu[TUC][PDEG + 1];
    __shared__ __align__(16) float s_w[SROWS][TUC];
    __shared__ float sC[SROWS * ROWF];          // 18.4 KB staged ctrl rows

    // warp 0 scans v-knots; warp 1 scans u-knots then computes u-basis
    if (wid == 0) {
        warp_scan_knots(knot_v + b * PL, sKv);
    } else if (wid == 1) {
        warp_scan_knots(knot_u + b * PL, sKu);
        __syncwarp();
        const int li = tid & 31;
        if (li < TUC) {
            float nu[PDEG + 1];
            const int us = basis_at(sKu, u[u0 + li], nu);
            s_iu[li] = us - PDEG;
            #pragma unroll
            for (int p = 0; p <= PDEG; p++) s_nu[li][p] = nu[p];
        }
    }
    __syncthreads();

    const float4* cb4 = (const float4*)(ctrl + (long)b * PNC * ROWF);

    // ---- prefetch first window (coalesced LDGs, overlap the basis chain) --
    const int rlo0 = s_iu[0];
    float4 pf[4];
    #pragma unroll
    for (int k = 0; k < 4; k++) {
        const int idx = tid + k * PS;
        const int j = idx / ROWV4, t4 = idx % ROWV4;
        const int row = min(rlo0 + j, PNC - 1);
        pf[k] = __ldg(&cb4[(long)row * ROWV4 + t4]);
    }

    // ---- v-basis (per thread, parallel; overlaps the LDGs above) ----
    float nv0, nv1, nv2, nv3;
    int iv;
    {
        float nv[PDEG + 1];
        iv = basis_at(sKv, v[vv], nv) - PDEG;
        nv0 = nv[0]; nv1 = nv[1]; nv2 = nv[2]; nv3 = nv[3];
    }

    float acc[TUC][PDIM];
    #pragma unroll
    for (int i = 0; i < TUC; i++) {
        acc[i][0] = 0.0f; acc[i][1] = 0.0f; acc[i][2] = 0.0f;
    }

    // grouped-window loop (block-uniform; typically a single iteration)
    int done = 0;
    bool first = true;
    while (done < TUC) {
        const int rlo = s_iu[done];
        int gend = done;
        while (gend + 1 < TUC && s_iu[gend + 1] + PDEG - rlo < SROWS) gend++;
        const int nrows = s_iu[gend] + PDEG - rlo + 1;   // <= SROWS

        if (!first) __syncthreads();   // prior iteration's reads complete

        // zero-padded weight table
        if (tid < SROWS * TUC) {
            const int j = tid / TUC, i = tid % TUC;
            float w = 0.0f;
            if (j < nrows && i >= done && i <= gend) {
                const int p = (rlo + j) - s_iu[i];
                if (p >= 0 && p <= PDEG) w = s_nu[i][p];
            }
            s_w[j][i] = w;
        }

        // stage ctrl rows [rlo, rlo+nrows)
        if (first) {
            #pragma unroll
            for (int k = 0; k < 4; k++)
                ((float4*)sC)[tid + k * PS] = pf[k];
            for (int idx = 4 * PS + tid; idx < nrows * ROWV4; idx += PS) {
                const int j = idx / ROWV4, t4 = idx % ROWV4;
                ((float4*)sC)[idx] = cb4[(long)(rlo + j) * ROWV4 + t4];
            }
        } else {                                // rare extra groups
            for (int idx = tid; idx < nrows * ROWV4; idx += PS) {
                const int j = idx / ROWV4, t4 = idx % ROWV4;
                ((float4*)sC)[idx] = cb4[(long)(rlo + j) * ROWV4 + t4];
            }
        }
        __syncthreads();

        // main loop: per row, scalar v-contract + 8-wide fanout
        // (weights via two broadcast LDS.128)
        for (int j = 0; j < nrows; j++) {
            const float* f = sC + j * ROWF + iv * PDIM;
            const float r0 = fmaf(nv0, f[0], fmaf(nv1, f[3], fmaf(nv2, f[6],  nv3 * f[9])));
            const float r1 = fmaf(nv0, f[1], fmaf(nv1, f[4], fmaf(nv2, f[7],  nv3 * f[10])));
            const float r2 = fmaf(nv0, f[2], fmaf(nv1, f[5], fmaf(nv2, f[8],  nv3 * f[11])));

            const float4 wa = ((const float4*)s_w[j])[0];   // broadcast
            const float4 wb = ((const float4*)s_w[j])[1];   // broadcast

            acc[0][0] = fmaf(wa.x, r0, acc[0][0]); acc[0][1] = fmaf(wa.x, r1, acc[0][1]); acc[0][2] = fmaf(wa.x, r2, acc[0][2]);
            acc[1][0] = fmaf(wa.y, r0, acc[1][0]); acc[1][1] = fmaf(wa.y, r1, acc[1][1]); acc[1][2] = fmaf(wa.y, r2, acc[1][2]);
            acc[2][0] = fmaf(wa.z, r0, acc[2][0]); acc[2][1] = fmaf(wa.z, r1, acc[2][1]); acc[2][2] = fmaf(wa.z, r2, acc[2][2]);
            acc[3][0] = fmaf(wa.w, r0, acc[3][0]); acc[3][1] = fmaf(wa.w, r1, acc[3][1]); acc[3][2] = fmaf(wa.w, r2, acc[3][2]);
            acc[4][0] = fmaf(wb.x, r0, acc[4][0]); acc[4][1] = fmaf(wb.x, r1, acc[4][1]); acc[4][2] = fmaf(wb.x, r2, acc[4][2]);
            acc[5][0] = fmaf(wb.y, r0, acc[5][0]); acc[5][1] = fmaf(wb.y, r1, acc[5][1]); acc[5][2] = fmaf(wb.y, r2, acc[5][2]);
            acc[6][0] = fmaf(wb.z, r0, acc[6][0]); acc[6][1] = fmaf(wb.z, r1, acc[6][1]); acc[6][2] = fmaf(wb.z, r2, acc[6][2]);
            acc[7][0] = fmaf(wb.w, r0, acc[7][0]); acc[7][1] = fmaf(wb.w, r1, acc[7][1]); acc[7][2] = fmaf(wb.w, r2, acc[7][2]);
        }

        first = false;
        done = gend + 1;
    }

    #pragma unroll
    for (int i = 0; i < TUC; i++) {
        float* o = out + (((long)b * PS + (u0 + i)) * PS + vv) * PDIM;
        o[0] = acc[i][0];
        o[1] = acc[i][1];
        o[2] = acc[i][2];
    }
}

// ---------------------------------------------------------------------------
extern "C" void kernel_launch(void* const* d_in, const int* in_sizes, int n_in,
                              void* d_out, int out_size)
{
    const float* ctrl   = (const float*)d_in[0];  // (B, 128, 128, 3)
    const float* knot_u = (const float*)d_in[1];  // (B, 132)
    const float* knot_v = (const float*)d_in[2];  // (B, 132)
    const float* u      = (const float*)d_in[3];  // (256,)
    const float* v      = (const float*)d_in[4];  // (256,)
    float* out = (float*)d_out;                   // (B, 256, 256, 3)

    surf_fused_kernel<<<PB * (PS / TUC), PS>>>(ctrl, knot_u, knot_v, u, v, out);
}

// round 16
// speedup vs baseline: 1.4147x; 1.0173x over previous
#include <cuda_runtime.h>
#include <cuda_bf16.h>

// Problem constants: P=Q=3, M=N=127, DIM=3, SU=SV=256, B=16
#define PB    16
#define PDEG  3
#define PM    127
#define PL    132          // knot vector length
#define PS    256          // samples per direction
#define PNC   128          // control points per direction
#define PDIM  3
#define PEPS  1e-8f
#define RG    4            // rows per block in rowsum kernel
#define TUC   8            // u's per block in ucontract kernel
#define GROWS 12           // zero-padded row window in ucontract kernel

// ---- device scratch (allocation-free) ----
__device__ float4 g_R[PB][PNC][PS];     // 8 MB rowsum scratch (L2-resident)

// ---------------------------------------------------------------------------
// One warp normalizes one knot vector entirely in registers, writes sK.
// cumsum order matches jnp.cumsum (sequential in index order).
// ---------------------------------------------------------------------------
__device__ __forceinline__ void warp_scan_knots(const float* __restrict__ knots,
                                                float* __restrict__ sK)
{
    const int lane = threadIdx.x & 31;
    const int CH = 5;                           // 32*5 >= 132
    const int base = lane * CH;
    float vch[CH];
    float run = 0.0f;
    #pragma unroll
    for (int k = 0; k < CH; k++) {
        int i = base + k;
        float x = 0.0f;
        if (i < PL) {
            x = knots[i];
            if (x < 0.0f) x = 0.0001f;
        }
        run += x;
        vch[k] = run;
    }
    float incl = run;
    #pragma unroll
    for (int off = 1; off < 32; off <<= 1) {
        float nb = __shfl_up_sync(0xffffffffu, incl, off);
        if (lane >= off) incl += nb;
    }
    const float excl = incl - run;
    const float sc0  = excl + vch[0];
    const float k0   = __shfl_sync(0xffffffffu, sc0, 0);
    const float last = __shfl_sync(0xffffffffu, incl, 31);
    const float inv  = 1.0f / (last - k0);
    #pragma unroll
    for (int k = 0; k < CH; k++) {
        int i = base + k;
        if (i < PL) sK[i] = ((excl + vch[k]) - k0) * inv;
    }
}

// span find (binary search + tie-walk, argmin semantics) + Cox-de Boor deg 3
__device__ __forceinline__ int basis_at(const float* sK, float t, float* Ni)
{
    int j;
    {
        const int cnt = PL - 2 * PDEG;          // 126
        int lo = 0, hi = cnt;
        while (lo < hi) {
            int mid = (lo + hi) >> 1;
            if (t - sK[PDEG + mid] > PEPS) lo = mid + 1;
            else hi = mid;
        }
        j = lo - 1;
        if (j < 0) j = 0;
        else {
            while (j > 0 && sK[PDEG + j - 1] == sK[PDEG + j]) j--;
        }
    }
    int span = j + PDEG;
    if (span < PDEG) span = PDEG;
    if (span > PM)   span = PM;

    Ni[0] = 1.0f; Ni[1] = 0.0f; Ni[2] = 0.0f; Ni[3] = 0.0f;
    #pragma unroll
    for (int k = 1; k <= PDEG; k++) {
        float saved = 0.0f;
        #pragma unroll
        for (int r = 0; r < PDEG; r++) {
            if (r >= k) break;
            float K1 = sK[span + r + 1];
            float K2 = sK[span + 1 - k + r];
            float denom = (K1 - t) + (t - K2);
            float temp = (denom == 0.0f) ? 0.0001f : __fdividef(Ni[r], denom);
            Ni[r] = saved + (K1 - t) * temp;
            saved = (t - K2) * temp;
        }
        Ni[k] = saved;
    }
    return span;
}

// ---------------------------------------------------------------------------
// Kernel 1: fused v-basis + rowsums.
// R[b][r][vv] = sum_q Nv[q][vv] * ctrl[b][r][iv+q][:]
// grid = B * (PNC/RG) = 512 blocks, blockDim = 256 (thread = vv).
// ---------------------------------------------------------------------------
__global__ void __launch_bounds__(PS)
surf_rowsum_kernel(const float* __restrict__ ctrl,
                   const float* __restrict__ knot_v,
                   const float* __restrict__ v)
{
    const int b     = blockIdx.x / (PNC / RG);
    const int rbase = (blockIdx.x % (PNC / RG)) * RG;
    const int vv    = threadIdx.x;
    const int wid   = threadIdx.x >> 5;

    __shared__ float sK[PL];
    if (wid == 0) warp_scan_knots(knot_v + b * PL, sK);
    __syncthreads();

    float nv[PDEG + 1];
    const int iv = basis_at(sK, v[vv], nv) - PDEG;

    const float* base = ctrl + (((long)b * PNC) * PNC + iv) * PDIM;

    #pragma unroll
    for (int j = 0; j < RG; j++) {
        const float* row = base + (long)(rbase + j) * (PNC * PDIM);
        float s0 = 0.0f, s1 = 0.0f, s2 = 0.0f;
        #pragma unroll
        for (int q = 0; q <= PDEG; q++) {
            const float w = nv[q];
            s0 = fmaf(w, __ldg(row + q * PDIM + 0), s0);
            s1 = fmaf(w, __ldg(row + q * PDIM + 1), s1);
            s2 = fmaf(w, __ldg(row + q * PDIM + 2), s2);
        }
        g_R[b][rbase + j][vv] = make_float4(s0, s1, s2, 0.0f);
    }
}

// ---------------------------------------------------------------------------
// Kernel 2: fused u-basis + u-contraction from global R.
// out[b][uu][vv] = sum_p nu[uu][p] * R[b][iu[uu]+p][vv]
// grid = B * (PS/TUC) = 512 blocks, blockDim = 256 (thread = vv).
// Per thread: ~12 coalesced LDG.128 + 288 FMA + 24 STG. No v-dependence.
// ---------------------------------------------------------------------------
__global__ void __launch_bounds__(PS)
surf_ucontract_kernel(const float* __restrict__ knot_u,
                      const float* __restrict__ u,
                      float* __restrict__ out)
{
    const int b   = blockIdx.x / (PS / TUC);
    const int u0  = (blockIdx.x % (PS / TUC)) * TUC;
    const int vv  = threadIdx.x;
    const int tid = threadIdx.x;
    const int wid = tid >> 5;

    __shared__ float sKu[PL];
    __shared__ int   s_iu[TUC];
    __shared__ float s_nu[TUC][PDEG + 1];
    __shared__ __align__(16) float s_w[GROWS][TUC];

    // warp 0: scan u-knots, then 8 lanes compute u-basis
    if (wid == 0) {
        warp_scan_knots(knot_u + b * PL, sKu);
        __syncwarp();
        const int li = tid & 31;
        if (li < TUC) {
            float nu[PDEG + 1];
            const int us = basis_at(sKu, u[u0 + li], nu);
            s_iu[li] = us - PDEG;
            #pragma unroll
            for (int p = 0; p <= PDEG; p++) s_nu[li][p] = nu[p];
        }
    }
    __syncthreads();

    float acc[TUC][PDIM];
    #pragma unroll
    for (int i = 0; i < TUC; i++) {
        acc[i][0] = 0.0f; acc[i][1] = 0.0f; acc[i][2] = 0.0f;
    }

    // grouped-window loop; typical case = one group of <= GROWS rows
    int done = 0;
    bool first = true;
    while (done < TUC) {
        const int rlo = s_iu[done];
        int gend = done;
        while (gend + 1 < TUC && s_iu[gend + 1] + PDEG - rlo < GROWS) gend++;

        if (!first) __syncthreads();            // prior reads of s_w complete

        // zero-padded weight table: w=0 for rows not in u i's window
        if (tid < GROWS * TUC) {
            const int j = tid / TUC, i = tid % TUC;
            float w = 0.0f;
            if (i >= done && i <= gend) {
                const int p = (rlo + j) - s_iu[i];
                if (p >= 0 && p <= PDEG) w = s_nu[i][p];
            }
            s_w[j][i] = w;
        }
        __syncthreads();

        // 12 fixed rows (clamped; clamped rows provably weight-0)
        #pragma unroll
        for (int j = 0; j < GROWS; j++) {
            const int row = min(rlo + j, PNC - 1);
            const float4 r = __ldg(&g_R[b][row][vv]);   // coalesced LDG.128

            const float4 wa = ((const float4*)s_w[j])[0];   // broadcast
            const float4 wb = ((const float4*)s_w[j])[1];   // broadcast

            acc[0][0] = fmaf(wa.x, r.x, acc[0][0]); acc[0][1] = fmaf(wa.x, r.y, acc[0][1]); acc[0][2] = fmaf(wa.x, r.z, acc[0][2]);
            acc[1][0] = fmaf(wa.y, r.x, acc[1][0]); acc[1][1] = fmaf(wa.y, r.y, acc[1][1]); acc[1][2] = fmaf(wa.y, r.z, acc[1][2]);
            acc[2][0] = fmaf(wa.z, r.x, acc[2][0]); acc[2][1] = fmaf(wa.z, r.y, acc[2][1]); acc[2][2] = fmaf(wa.z, r.z, acc[2][2]);
            acc[3][0] = fmaf(wa.w, r.x, acc[3][0]); acc[3][1] = fmaf(wa.w, r.y, acc[3][1]); acc[3][2] = fmaf(wa.w, r.z, acc[3][2]);
            acc[4][0] = fmaf(wb.x, r.x, acc[4][0]); acc[4][1] = fmaf(wb.x, r.y, acc[4][1]); acc[4][2] = fmaf(wb.x, r.z, acc[4][2]);
            acc[5][0] = fmaf(wb.y, r.x, acc[5][0]); acc[5][1] = fmaf(wb.y, r.y, acc[5][1]); acc[5][2] = fmaf(wb.y, r.z, acc[5][2]);
            acc[6][0] = fmaf(wb.z, r.x, acc[6][0]); acc[6][1] = fmaf(wb.z, r.y, acc[6][1]); acc[6][2] = fmaf(wb.z, r.z, acc[6][2]);
            acc[7][0] = fmaf(wb.w, r.x, acc[7][0]); acc[7][1] = fmaf(wb.w, r.y, acc[7][1]); acc[7][2] = fmaf(wb.w, r.z, acc[7][2]);
        }

        first = false;
        done = gend + 1;
    }

    #pragma unroll
    for (int i = 0; i < TUC; i++) {
        float* o = out + (((long)b * PS + (u0 + i)) * PS + vv) * PDIM;
        o[0] = acc[i][0];
        o[1] = acc[i][1];
        o[2] = acc[i][2];
    }
}

// ---------------------------------------------------------------------------
extern "C" void kernel_launch(void* const* d_in, const int* in_sizes, int n_in,
                              void* d_out, int out_size)
{
    const float* ctrl   = (const float*)d_in[0];  // (B, 128, 128, 3)
    const float* knot_u = (const float*)d_in[1];  // (B, 132)
    const float* knot_v = (const float*)d_in[2];  // (B, 132)
    const float* u      = (const float*)d_in[3];  // (256,)
    const float* v      = (const float*)d_in[4];  // (256,)
    float* out = (float*)d_out;                   // (B, 256, 256, 3)

    surf_rowsum_kernel<<<PB * (PNC / RG), PS>>>(ctrl, knot_v, v);
    surf_ucontract_kernel<<<PB * (PS / TUC), PS>>>(knot_u, u, out);
}